// round 11
// baseline (speedup 1.0000x reference)
#include <cuda_runtime.h>
#include <cuda_bf16.h>

// PositionEmbeddingSine — single-kernel version.
// Per block: n_batches binary searches (coords[:,0] sorted) -> s_start[] in smem.
// Main loop: warp-centric, 4 rows / warp-iteration, front-batched int4 loads (MLP=4),
// lane owns freq pairs p0=2*(lane&15), p1=p0+1 -> one float4 (STG.128.CS) per round,
// 6 rounds cover (4 rows) x (3 dims). Output is write-once -> streaming stores.

#define SCALE_2PI 6.283185307179586f
#define EPS_F 1e-6f
#define L2T32 (13.287712379549449f / 32.0f)   // log2(10000)/32
#define MAX_B 64

__global__ void __launch_bounds__(256) pes_main_kernel(
    const int4* __restrict__ coords,   // [M] rows: (b, x, y, z)
    const int* __restrict__ psx,
    const int* __restrict__ psy,
    const int* __restrict__ psz,
    const int* __restrict__ pnb,
    const int* __restrict__ pml,
    float* __restrict__ out,
    int M)
{
    __shared__ int s_start[MAX_B];

    const int nb = min(__ldg(pnb), MAX_B);

    // Per-block batch-start table: first index m with coords[m].x >= tid.
    if (threadIdx.x < (unsigned)nb) {
        int target = threadIdx.x;
        int lo = 0, hi = M;                  // invariant: coords[<lo].x < target <= coords[>=hi].x
        while (lo < hi) {
            int mid = (lo + hi) >> 1;
            if (__ldg(&coords[mid].x) < target) lo = mid + 1;
            else hi = mid;
        }
        s_start[target] = lo;
    }
    __syncthreads();

    const int lane = threadIdx.x & 31;
    const int k16  = lane & 15;
    const int hiL  = lane >> 4;            // 0 or 1
    const int warp = (blockIdx.x * blockDim.x + threadIdx.x) >> 5;
    const int nw   = (gridDim.x * blockDim.x) >> 5;

    const int max_len = __ldg(pml);

    const float g0 = SCALE_2PI / ((float)(__ldg(psx) - 1) + EPS_F);
    const float g1 = SCALE_2PI / ((float)(__ldg(psy) - 1) + EPS_F);
    const float g2 = SCALE_2PI / ((float)(__ldg(psz) - 1) + EPS_F);

    // This lane's two frequency scales (loop-invariant).
    const float invA = exp2f(-(float)(2 * k16)     * L2T32);
    const float invB = exp2f(-(float)(2 * k16 + 1) * L2T32);

    const int laneoff = 4 * k16;

    for (int m0 = warp * 4; m0 < M; m0 += nw * 4) {
        // Front-batched independent loads (MLP=4).
        int4 c[4];
        #pragma unroll
        for (int k = 0; k < 4; k++) {
            int mk = m0 + k;
            c[k] = __ldg(&coords[mk < M ? mk : M - 1]);
        }

        float* r[4];
        #pragma unroll
        for (int k = 0; k < 4; k++) {
            int mk = m0 + k;
            r[k] = out + ((long long)c[k].x * max_len + (mk - s_start[c[k].x])) * 192;
        }

        // v[dim] for dim = row*3 + d
        float v[12];
        #pragma unroll
        for (int k = 0; k < 4; k++) {
            v[3 * k + 0] = (float)c[k].y * g0;
            v[3 * k + 1] = (float)c[k].z * g1;
            v[3 * k + 2] = (float)c[k].w * g2;
        }

        #pragma unroll
        for (int t = 0; t < 6; t++) {
            const int dim = 2 * t + hiL;
            const int row = dim / 3;
            const int d   = dim - 3 * row;
            float a = v[dim];
            float sa, ca, sb, cb;
            __sincosf(a * invA, &sa, &ca);
            __sincosf(a * invB, &sb, &cb);
            if (m0 + row < M) {
                __stcs((float4*)(r[row] + d * 64 + laneoff),
                       make_float4(sa, ca, sb, cb));
            }
        }
    }
}

extern "C" void kernel_launch(void* const* d_in, const int* in_sizes, int n_in,
                              void* d_out, int out_size)
{
    const int* coords = (const int*)d_in[0];
    const int* psx    = (const int*)d_in[1];
    const int* psy    = (const int*)d_in[2];
    const int* psz    = (const int*)d_in[3];
    const int* pnb    = (const int*)d_in[4];
    const int* pml    = (const int*)d_in[5];
    float* out        = (float*)d_out;

    int M = in_sizes[0] / 4;

    int threads = 256;
    int blocks = 148 * 8;
    pes_main_kernel<<<blocks, threads>>>((const int4*)coords, psx, psy, psz, pnb, pml, out, M);
}

// round 17
// speedup vs baseline: 1.1028x; 1.1028x over previous
#include <cuda_runtime.h>
#include <cuda_bf16.h>

// PositionEmbeddingSine — single launch, R3 mainloop (regs=32, full occupancy).
// Per block: n_batches binary searches (coords[:,0] sorted) -> s_start[] in smem.
// Main loop: lane = freq pair j; warp grid-strides over rows; 3x (sincos + float2 store).

#define SCALE_2PI 6.283185307179586f
#define EPS_F 1e-6f
#define L2T32 (13.287712379549449f / 32.0f)   // log2(10000)/32
#define MAX_B 64

__global__ void __launch_bounds__(256) pes_main_kernel(
    const int4* __restrict__ coords,   // [M] rows: (b, x, y, z)
    const int* __restrict__ psx,
    const int* __restrict__ psy,
    const int* __restrict__ psz,
    const int* __restrict__ pnb,
    const int* __restrict__ pml,
    float* __restrict__ out,
    int M)
{
    __shared__ int s_start[MAX_B];

    const int nb = min(__ldg(pnb), MAX_B);

    // Per-block batch-start table: first index m with coords[m].x >= tid.
    if (threadIdx.x < (unsigned)nb) {
        int target = threadIdx.x;
        int lo = 0, hi = M;
        while (lo < hi) {
            int mid = (lo + hi) >> 1;
            if (__ldg(&coords[mid].x) < target) lo = mid + 1;
            else hi = mid;
        }
        s_start[target] = lo;
    }
    __syncthreads();

    const int lane   = threadIdx.x & 31;
    const int warp   = (blockIdx.x * blockDim.x + threadIdx.x) >> 5;
    const int nwarps = (gridDim.x * blockDim.x) >> 5;

    const int max_len = __ldg(pml);

    // Per-thread loop invariants: combined scale for each spatial dim at this lane's freq.
    const float inv_dim = exp2f(-(float)lane * L2T32);   // 10000^(-lane/32)
    const float fx = (SCALE_2PI / ((float)(__ldg(psx) - 1) + EPS_F)) * inv_dim;
    const float fy = (SCALE_2PI / ((float)(__ldg(psy) - 1) + EPS_F)) * inv_dim;
    const float fz = (SCALE_2PI / ((float)(__ldg(psz) - 1) + EPS_F)) * inv_dim;

    for (int m = warp; m < M; m += nwarps) {
        int4 c = __ldg(&coords[m]);                 // broadcast across warp
        int slot = m - s_start[c.x];
        float* orow = out + ((long long)c.x * max_len + slot) * 192 + 2 * lane;

        float sn, cs;
        __sincosf((float)c.y * fx, &sn, &cs);
        *(float2*)(orow)       = make_float2(sn, cs);
        __sincosf((float)c.z * fy, &sn, &cs);
        *(float2*)(orow + 64)  = make_float2(sn, cs);
        __sincosf((float)c.w * fz, &sn, &cs);
        *(float2*)(orow + 128) = make_float2(sn, cs);
    }
}

extern "C" void kernel_launch(void* const* d_in, const int* in_sizes, int n_in,
                              void* d_out, int out_size)
{
    const int* coords = (const int*)d_in[0];
    const int* psx    = (const int*)d_in[1];
    const int* psy    = (const int*)d_in[2];
    const int* psz    = (const int*)d_in[3];
    const int* pnb    = (const int*)d_in[4];
    const int* pml    = (const int*)d_in[5];
    float* out        = (float*)d_out;

    int M = in_sizes[0] / 4;

    int threads = 256;
    int blocks = 148 * 8;   // one full wave at 8 blocks/SM residency
    pes_main_kernel<<<blocks, threads>>>((const int4*)coords, psx, psy, psz, pnb, pml, out, M);
}